// round 2
// baseline (speedup 1.0000x reference)
#include <cuda_runtime.h>
#include <math.h>

#define NSQ    64
#define EPS_F  1e-6f
#define TRUNC  0.1f
#define PSTRIDE 22

__device__ __forceinline__ float fast_lg2(float x) {
    float r;
    asm("lg2.approx.f32 %0, %1;" : "=f"(r) : "f"(x));
    return r;
}
__device__ __forceinline__ float fast_ex2(float x) {
    float r;
    asm("ex2.approx.f32 %0, %1;" : "=f"(r) : "f"(x));
    return r;
}

__global__ void __launch_bounds__(256, 4)
superq_kernel(const float* __restrict__ raw_scale,   // [64,3]
              const float* __restrict__ raw_exp,     // [64,2]
              const float* __restrict__ raw_rot,     // [64,4]
              const float* __restrict__ trans,       // [64,3]
              const float* __restrict__ points,      // [P,3]
              float* __restrict__ out,               // [P] sdf ; [P,3] normals
              int P)
{
    __shared__ float sp[NSQ * PSTRIDE];
    const int tid = threadIdx.x;

    if (tid < NSQ) {
        const int i = tid;
        float* c = sp + i * PSTRIDE;
        float qw = raw_rot[4*i+0], qx = raw_rot[4*i+1];
        float qy = raw_rot[4*i+2], qz = raw_rot[4*i+3];
        float qn = 1.0f / sqrtf(qw*qw + qx*qx + qy*qy + qz*qz);
        qw *= qn; qx *= qn; qy *= qn; qz *= qn;
        c[0] = 1.0f - 2.0f*(qy*qy + qz*qz);
        c[1] = 2.0f*(qx*qy - qw*qz);
        c[2] = 2.0f*(qx*qz + qw*qy);
        c[3] = 2.0f*(qx*qy + qw*qz);
        c[4] = 1.0f - 2.0f*(qx*qx + qz*qz);
        c[5] = 2.0f*(qy*qz - qw*qx);
        c[6] = 2.0f*(qx*qz - qw*qy);
        c[7] = 2.0f*(qy*qz + qw*qx);
        c[8] = 1.0f - 2.0f*(qx*qx + qy*qy);
        c[9]  = trans[3*i+0];
        c[10] = trans[3*i+1];
        c[11] = trans[3*i+2];
        c[12] = expf(-2.0f * raw_scale[3*i+0]);
        c[13] = expf(-2.0f * raw_scale[3*i+1]);
        c[14] = expf(-2.0f * raw_scale[3*i+2]);
        float e1 = 0.1f + 1.8f / (1.0f + expf(-raw_exp[2*i+0]));
        float e2 = 0.1f + 1.8f / (1.0f + expf(-raw_exp[2*i+1]));
        c[15] = 1.0f / e2;
        c[16] = 1.0f / e1;
        c[17] = e2 / e1;
        c[18] = -0.5f * e1;
        c[19] = -0.5f * e1 - 1.0f;
        c[20] = e2 / e1 - 1.0f;
    }
    __syncthreads();

    const int p = blockIdx.x * blockDim.x + tid;
    if (p >= P) return;

    const float px = points[3*p+0];
    const float py = points[3*p+1];
    const float pz = points[3*p+2];

    float best  = 3.0e38f;
    float bgx = 0.0f, bgy = 0.0f, bgz = 0.0f;

#pragma unroll 2
    for (int i = 0; i < NSQ; i++) {
        const float* c = sp + i * PSTRIDE;
        const float dx = px - c[9], dy = py - c[10], dz = pz - c[11];
        const float xc = c[0]*dx + c[3]*dy + c[6]*dz;
        const float yc = c[1]*dx + c[4]*dy + c[7]*dz;
        const float zc = c[2]*dx + c[5]*dy + c[8]*dz;
        const float axv = fabsf(xc), ayv = fabsf(yc), azv = fabsf(zc);
        const bool mx = axv > EPS_F, my = ayv > EPS_F, mz = azv > EPS_F;
        const float cx = fmaxf(axv, EPS_F);
        const float cy = fmaxf(ayv, EPS_F);
        const float cz = fmaxf(azv, EPS_F);
        const float X = (xc > 0.0f) ? cx : -cx;
        const float Y = (yc > 0.0f) ? cy : -cy;
        const float Z = (zc > 0.0f) ? cz : -cz;

        const float x2 = X*X, y2 = Y*Y, z2 = Z*Z;
        const float r2  = x2 + y2 + z2;
        const float ir0 = rsqrtf(r2);
        const float r0  = r2 * ir0;

        const float lx = fast_lg2(x2 * c[12]);
        const float ly = fast_lg2(y2 * c[13]);
        const float lz = fast_lg2(z2 * c[14]);
        const float ie2 = c[15], ie1 = c[16];
        const float t1 = fast_ex2(ie2 * lx);
        const float t2 = fast_ex2(ie2 * ly);
        const float t3 = fast_ex2(ie1 * lz);

        const float A  = t1 + t2 + EPS_F;
        const float lA = fast_lg2(A);
        const float B  = fast_ex2(c[17] * lA) + t3;   // A^(e2/e1) + t3
        const float lB = fast_lg2(B);
        const float f  = fast_ex2(c[18] * lB);        // B^(-e1/2)

        const float omf = 1.0f - f;
        float s = r0 * omf;
        s = fminf(fmaxf(s, -TRUNC), TRUNC);

        const float D  = fast_ex2(c[19] * lB);        // B^(-e1/2-1)
        const float C  = fast_ex2(c[20] * lA);        // A^(e2/e1-1)
        const float su = ir0 * omf;
        const float rD  = r0 * D;
        const float Kxy = rD * C;
        const float gx = mx ? fmaf(X, su, __fdividef(Kxy * t1, X)) : 0.0f;
        const float gy = my ? fmaf(Y, su, __fdividef(Kxy * t2, Y)) : 0.0f;
        const float gz = mz ? fmaf(Z, su, __fdividef(rD  * t3, Z)) : 0.0f;

        const float gwx = c[0]*gx + c[1]*gy + c[2]*gz;
        const float gwy = c[3]*gx + c[4]*gy + c[5]*gz;
        const float gwz = c[6]*gx + c[7]*gy + c[8]*gz;

        if (s < best) { best = s; bgx = gwx; bgy = gwy; bgz = gwz; }
    }

    const float gn  = sqrtf(bgx*bgx + bgy*bgy + bgz*bgz);
    const float inv = 1.0f / fmaxf(gn, 1e-12f);

    out[p] = best;
    float* no = out + P;
    no[3*p+0] = bgx * inv;
    no[3*p+1] = bgy * inv;
    no[3*p+2] = bgz * inv;
}

extern "C" void kernel_launch(void* const* d_in, const int* in_sizes, int n_in,
                              void* d_out, int out_size)
{
    const float* raw_scale = (const float*)d_in[0];
    const float* raw_exp   = (const float*)d_in[1];
    const float* raw_rot   = (const float*)d_in[2];
    const float* trans     = (const float*)d_in[3];
    const float* points    = (const float*)d_in[4];
    float* out = (float*)d_out;

    const int P = in_sizes[4] / 3;
    const int threads = 256;
    const int blocks  = (P + threads - 1) / threads;
    superq_kernel<<<blocks, threads>>>(raw_scale, raw_exp, raw_rot, trans,
                                       points, out, P);
}

// round 3
// speedup vs baseline: 1.1103x; 1.1103x over previous
#include <cuda_runtime.h>
#include <math.h>

#define NSQ    64
#define EPS_F  1e-6f
#define TRUNC  0.1f
// 5 float4 per prim:
// q0 = {r00,r01,r02, tbx}   (tb = R^T t)
// q1 = {r10,r11,r12, tby}
// q2 = {r20,r21,r22, tbz}
// q3 = {isx2,isy2,isz2, ie2}
// q4 = {ie1, e2/e1, -e1/2, pad}
#define PQ 5

__device__ __forceinline__ float fast_lg2(float x) {
    float r; asm("lg2.approx.f32 %0, %1;" : "=f"(r) : "f"(x)); return r;
}
__device__ __forceinline__ float fast_ex2(float x) {
    float r; asm("ex2.approx.f32 %0, %1;" : "=f"(r) : "f"(x)); return r;
}
__device__ __forceinline__ float fast_rcp(float x) {
    float r; asm("rcp.approx.f32 %0, %1;" : "=f"(r) : "f"(x)); return r;
}

__global__ void __launch_bounds__(256, 4)
superq_kernel(const float* __restrict__ raw_scale,   // [64,3]
              const float* __restrict__ raw_exp,     // [64,2]
              const float* __restrict__ raw_rot,     // [64,4]
              const float* __restrict__ trans,       // [64,3]
              const float* __restrict__ points,      // [P,3]
              float* __restrict__ out,               // [P] sdf ; [P,3] normals
              int P)
{
    __shared__ float4 sp[NSQ * PQ];
    const int tid = threadIdx.x;

    if (tid < NSQ) {
        const int i = tid;
        float qw = raw_rot[4*i+0], qx = raw_rot[4*i+1];
        float qy = raw_rot[4*i+2], qz = raw_rot[4*i+3];
        float qn = 1.0f / sqrtf(qw*qw + qx*qx + qy*qy + qz*qz);
        qw *= qn; qx *= qn; qy *= qn; qz *= qn;
        const float r00 = 1.0f - 2.0f*(qy*qy + qz*qz);
        const float r01 = 2.0f*(qx*qy - qw*qz);
        const float r02 = 2.0f*(qx*qz + qw*qy);
        const float r10 = 2.0f*(qx*qy + qw*qz);
        const float r11 = 1.0f - 2.0f*(qx*qx + qz*qz);
        const float r12 = 2.0f*(qy*qz - qw*qx);
        const float r20 = 2.0f*(qx*qz - qw*qy);
        const float r21 = 2.0f*(qy*qz + qw*qx);
        const float r22 = 1.0f - 2.0f*(qx*qx + qy*qy);
        const float tx = trans[3*i+0], ty = trans[3*i+1], tz = trans[3*i+2];
        // tb = R^T t  (so Xc = R^T p - tb)
        const float tbx = r00*tx + r10*ty + r20*tz;
        const float tby = r01*tx + r11*ty + r21*tz;
        const float tbz = r02*tx + r12*ty + r22*tz;
        const float isx2 = expf(-2.0f * raw_scale[3*i+0]);
        const float isy2 = expf(-2.0f * raw_scale[3*i+1]);
        const float isz2 = expf(-2.0f * raw_scale[3*i+2]);
        const float e1 = 0.1f + 1.8f / (1.0f + expf(-raw_exp[2*i+0]));
        const float e2 = 0.1f + 1.8f / (1.0f + expf(-raw_exp[2*i+1]));
        sp[i*PQ+0] = make_float4(r00, r01, r02, tbx);
        sp[i*PQ+1] = make_float4(r10, r11, r12, tby);
        sp[i*PQ+2] = make_float4(r20, r21, r22, tbz);
        sp[i*PQ+3] = make_float4(isx2, isy2, isz2, 1.0f/e2);
        sp[i*PQ+4] = make_float4(1.0f/e1, e2/e1, -0.5f*e1, 0.0f);
    }
    __syncthreads();

    const int p = blockIdx.x * blockDim.x + tid;
    if (p >= P) return;

    const float px = points[3*p+0];
    const float py = points[3*p+1];
    const float pz = points[3*p+2];

    float best = 3.0e38f;
    float bgx = 0.0f, bgy = 0.0f, bgz = 0.0f;

#pragma unroll 2
    for (int i = 0; i < NSQ; i++) {
        const float4 q0 = sp[i*PQ+0];
        const float4 q1 = sp[i*PQ+1];
        const float4 q2 = sp[i*PQ+2];
        const float4 q3 = sp[i*PQ+3];
        const float4 q4 = sp[i*PQ+4];

        // Xc = R^T p - R^T t
        const float xc = q0.x*px + q1.x*py + q2.x*pz - q0.w;
        const float yc = q0.y*px + q1.y*py + q2.y*pz - q1.w;
        const float zc = q0.z*px + q1.z*py + q2.z*pz - q2.w;

        const float axv = fabsf(xc), ayv = fabsf(yc), azv = fabsf(zc);
        const bool mx = axv > EPS_F, my = ayv > EPS_F, mz = azv > EPS_F;
        // signed clamp away from zero (cx>0, so copysign == sgn*cx)
        const float X = copysignf(fmaxf(axv, EPS_F), xc);
        const float Y = copysignf(fmaxf(ayv, EPS_F), yc);
        const float Z = copysignf(fmaxf(azv, EPS_F), zc);

        const float x2 = X*X, y2 = Y*Y, z2 = Z*Z;
        const float r2  = x2 + y2 + z2;
        const float ir0 = rsqrtf(r2);
        const float r0  = r2 * ir0;

        const float lx = fast_lg2(x2 * q3.x);
        const float ly = fast_lg2(y2 * q3.y);
        const float lz = fast_lg2(z2 * q3.z);
        const float t1 = fast_ex2(q3.w * lx);
        const float t2 = fast_ex2(q3.w * ly);
        const float t3 = fast_ex2(q4.x * lz);

        const float A    = t1 + t2 + EPS_F;
        const float lA   = fast_lg2(A);
        const float aAp  = q4.y * lA;          // (e2/e1)*lA
        const float Apow = fast_ex2(aAp);
        const float C    = fast_ex2(aAp - lA); // A^(e2/e1-1)
        const float B    = Apow + t3;
        const float lB   = fast_lg2(B);
        const float af   = q4.z * lB;          // (-e1/2)*lB
        const float f    = fast_ex2(af);
        const float D    = fast_ex2(af - lB);  // B^(-e1/2-1)

        const float omf = 1.0f - f;
        float s = r0 * omf;
        s = fminf(fmaxf(s, -TRUNC), TRUNC);

        // shared reciprocal for the three signed divides
        const float XY = X*Y, YZ = Y*Z, XZ = X*Z;
        const float rP = fast_rcp(XY * Z);
        const float iX = YZ * rP, iY = XZ * rP, iZ = XY * rP;

        const float su  = ir0 * omf;
        const float rD  = r0 * D;
        const float Kxy = rD * C;
        const float gx = mx ? fmaf(X, su, (Kxy * t1) * iX) : 0.0f;
        const float gy = my ? fmaf(Y, su, (Kxy * t2) * iY) : 0.0f;
        const float gz = mz ? fmaf(Z, su, (rD  * t3) * iZ) : 0.0f;

        // world-frame gradient: g = R * gX
        const float gwx = q0.x*gx + q0.y*gy + q0.z*gz;
        const float gwy = q1.x*gx + q1.y*gy + q1.z*gz;
        const float gwz = q2.x*gx + q2.y*gy + q2.z*gz;

        const bool upd = s < best;
        best = upd ? s   : best;
        bgx  = upd ? gwx : bgx;
        bgy  = upd ? gwy : bgy;
        bgz  = upd ? gwz : bgz;
    }

    const float gn  = sqrtf(bgx*bgx + bgy*bgy + bgz*bgz);
    const float inv = 1.0f / fmaxf(gn, 1e-12f);

    out[p] = best;
    float* no = out + P;
    no[3*p+0] = bgx * inv;
    no[3*p+1] = bgy * inv;
    no[3*p+2] = bgz * inv;
}

extern "C" void kernel_launch(void* const* d_in, const int* in_sizes, int n_in,
                              void* d_out, int out_size)
{
    const float* raw_scale = (const float*)d_in[0];
    const float* raw_exp   = (const float*)d_in[1];
    const float* raw_rot   = (const float*)d_in[2];
    const float* trans     = (const float*)d_in[3];
    const float* points    = (const float*)d_in[4];
    float* out = (float*)d_out;

    const int P = in_sizes[4] / 3;
    const int threads = 256;
    const int blocks  = (P + threads - 1) / threads;
    superq_kernel<<<blocks, threads>>>(raw_scale, raw_exp, raw_rot, trans,
                                       points, out, P);
}

// round 4
// speedup vs baseline: 1.7055x; 1.5361x over previous
#include <cuda_runtime.h>
#include <math.h>

#define NSQ    64
#define EPS_F  1e-6f
#define EPS2_F (1e-6f * 1e-6f)
#define TRUNC  0.1f
// 5 float4 per prim:
// q0 = {r00,r01,r02, tbx}   (tb = R^T t)
// q1 = {r10,r11,r12, tby}
// q2 = {r20,r21,r22, tbz}
// q3 = {isx2,isy2,isz2, 1/e2}
// q4 = {1/e1, e2/e1, -e1/2, pad}
#define PQ 5

__device__ __forceinline__ float fast_lg2(float x) {
    float r; asm("lg2.approx.f32 %0, %1;" : "=f"(r) : "f"(x)); return r;
}
__device__ __forceinline__ float fast_ex2(float x) {
    float r; asm("ex2.approx.f32 %0, %1;" : "=f"(r) : "f"(x)); return r;
}
__device__ __forceinline__ float fast_rcp(float x) {
    float r; asm("rcp.approx.f32 %0, %1;" : "=f"(r) : "f"(x)); return r;
}
__device__ __forceinline__ float fast_sqrt(float x) {
    float r; asm("sqrt.approx.f32 %0, %1;" : "=f"(r) : "f"(x)); return r;
}

__global__ void __launch_bounds__(256, 5)
superq_kernel(const float* __restrict__ raw_scale,   // [64,3]
              const float* __restrict__ raw_exp,     // [64,2]
              const float* __restrict__ raw_rot,     // [64,4]
              const float* __restrict__ trans,       // [64,3]
              const float* __restrict__ points,      // [P,3]
              float* __restrict__ out,               // [P] sdf ; [P,3] normals
              int P)
{
    __shared__ float4 sp[NSQ * PQ];
    const int tid = threadIdx.x;

    if (tid < NSQ) {
        const int i = tid;
        float qw = raw_rot[4*i+0], qx = raw_rot[4*i+1];
        float qy = raw_rot[4*i+2], qz = raw_rot[4*i+3];
        float qn = 1.0f / sqrtf(qw*qw + qx*qx + qy*qy + qz*qz);
        qw *= qn; qx *= qn; qy *= qn; qz *= qn;
        const float r00 = 1.0f - 2.0f*(qy*qy + qz*qz);
        const float r01 = 2.0f*(qx*qy - qw*qz);
        const float r02 = 2.0f*(qx*qz + qw*qy);
        const float r10 = 2.0f*(qx*qy + qw*qz);
        const float r11 = 1.0f - 2.0f*(qx*qx + qz*qz);
        const float r12 = 2.0f*(qy*qz - qw*qx);
        const float r20 = 2.0f*(qx*qz - qw*qy);
        const float r21 = 2.0f*(qy*qz + qw*qx);
        const float r22 = 1.0f - 2.0f*(qx*qx + qy*qy);
        const float tx = trans[3*i+0], ty = trans[3*i+1], tz = trans[3*i+2];
        const float tbx = r00*tx + r10*ty + r20*tz;
        const float tby = r01*tx + r11*ty + r21*tz;
        const float tbz = r02*tx + r12*ty + r22*tz;
        const float isx2 = expf(-2.0f * raw_scale[3*i+0]);
        const float isy2 = expf(-2.0f * raw_scale[3*i+1]);
        const float isz2 = expf(-2.0f * raw_scale[3*i+2]);
        const float e1 = 0.1f + 1.8f / (1.0f + expf(-raw_exp[2*i+0]));
        const float e2 = 0.1f + 1.8f / (1.0f + expf(-raw_exp[2*i+1]));
        sp[i*PQ+0] = make_float4(r00, r01, r02, tbx);
        sp[i*PQ+1] = make_float4(r10, r11, r12, tby);
        sp[i*PQ+2] = make_float4(r20, r21, r22, tbz);
        sp[i*PQ+3] = make_float4(isx2, isy2, isz2, 1.0f/e2);
        sp[i*PQ+4] = make_float4(1.0f/e1, e2/e1, -0.5f*e1, 0.0f);
    }
    __syncthreads();

    const int p = blockIdx.x * blockDim.x + tid;
    if (p >= P) return;

    const float px = points[3*p+0];
    const float py = points[3*p+1];
    const float pz = points[3*p+2];

    float best = 3.0e38f;
    int   bi   = 0;

    // ---- Pass 1: sdf-only argmin (squares only; no signs, no gradient) ----
#pragma unroll 4
    for (int i = 0; i < NSQ; i++) {
        const float4 q0 = sp[i*PQ+0];
        const float4 q1 = sp[i*PQ+1];
        const float4 q2 = sp[i*PQ+2];
        const float4 q3 = sp[i*PQ+3];
        const float4 q4 = sp[i*PQ+4];

        const float xc = q0.x*px + q1.x*py + q2.x*pz - q0.w;
        const float yc = q0.y*px + q1.y*py + q2.y*pz - q1.w;
        const float zc = q0.z*px + q1.z*py + q2.z*pz - q2.w;

        // max(|x|,eps)^2 == max(x^2, eps^2) exactly (monotone + correct rounding)
        const float x2 = fmaxf(xc*xc, EPS2_F);
        const float y2 = fmaxf(yc*yc, EPS2_F);
        const float z2 = fmaxf(zc*zc, EPS2_F);

        const float r2 = x2 + y2 + z2;
        const float r0 = fast_sqrt(r2);

        const float t1 = fast_ex2(q3.w * fast_lg2(x2 * q3.x));
        const float t2 = fast_ex2(q3.w * fast_lg2(y2 * q3.y));
        const float t3 = fast_ex2(q4.x * fast_lg2(z2 * q3.z));

        const float A  = t1 + t2 + EPS_F;
        const float B  = fast_ex2(q4.y * fast_lg2(A)) + t3;
        const float f  = fast_ex2(q4.z * fast_lg2(B));

        float s = fmaf(-r0, f, r0);            // r0*(1-f)
        s = fminf(fmaxf(s, -TRUNC), TRUNC);

        const bool upd = s < best;             // strict <: first-min wins
        best = upd ? s : best;
        bi   = upd ? i : bi;
    }

    // ---- Pass 2: gradient for the single winning prim ----
    {
        const float4 q0 = sp[bi*PQ+0];
        const float4 q1 = sp[bi*PQ+1];
        const float4 q2 = sp[bi*PQ+2];
        const float4 q3 = sp[bi*PQ+3];
        const float4 q4 = sp[bi*PQ+4];

        const float xc = q0.x*px + q1.x*py + q2.x*pz - q0.w;
        const float yc = q0.y*px + q1.y*py + q2.y*pz - q1.w;
        const float zc = q0.z*px + q1.z*py + q2.z*pz - q2.w;

        const float axv = fabsf(xc), ayv = fabsf(yc), azv = fabsf(zc);
        const bool mx = axv > EPS_F, my = ayv > EPS_F, mz = azv > EPS_F;
        const float X = copysignf(fmaxf(axv, EPS_F), xc);
        const float Y = copysignf(fmaxf(ayv, EPS_F), yc);
        const float Z = copysignf(fmaxf(azv, EPS_F), zc);

        const float x2 = X*X, y2 = Y*Y, z2 = Z*Z;
        const float r2  = x2 + y2 + z2;
        const float ir0 = rsqrtf(r2);
        const float r0  = r2 * ir0;

        const float t1 = fast_ex2(q3.w * fast_lg2(x2 * q3.x));
        const float t2 = fast_ex2(q3.w * fast_lg2(y2 * q3.y));
        const float t3 = fast_ex2(q4.x * fast_lg2(z2 * q3.z));

        const float A    = t1 + t2 + EPS_F;
        const float lA   = fast_lg2(A);
        const float aAp  = q4.y * lA;
        const float Apow = fast_ex2(aAp);
        const float C    = fast_ex2(aAp - lA);   // A^(e2/e1-1)
        const float B    = Apow + t3;
        const float lB   = fast_lg2(B);
        const float af   = q4.z * lB;
        const float f    = fast_ex2(af);
        const float D    = fast_ex2(af - lB);    // B^(-e1/2-1)

        const float omf = 1.0f - f;

        const float XY = X*Y, YZ = Y*Z, XZ = X*Z;
        const float rP = fast_rcp(XY * Z);
        const float iX = YZ * rP, iY = XZ * rP, iZ = XY * rP;

        const float su  = ir0 * omf;
        const float rD  = r0 * D;
        const float Kxy = rD * C;
        const float gx = mx ? fmaf(X, su, (Kxy * t1) * iX) : 0.0f;
        const float gy = my ? fmaf(Y, su, (Kxy * t2) * iY) : 0.0f;
        const float gz = mz ? fmaf(Z, su, (rD  * t3) * iZ) : 0.0f;

        const float gwx = q0.x*gx + q0.y*gy + q0.z*gz;
        const float gwy = q1.x*gx + q1.y*gy + q1.z*gz;
        const float gwz = q2.x*gx + q2.y*gy + q2.z*gz;

        const float gn  = sqrtf(gwx*gwx + gwy*gwy + gwz*gwz);
        const float inv = 1.0f / fmaxf(gn, 1e-12f);

        out[p] = best;
        float* no = out + P;
        no[3*p+0] = gwx * inv;
        no[3*p+1] = gwy * inv;
        no[3*p+2] = gwz * inv;
    }
}

extern "C" void kernel_launch(void* const* d_in, const int* in_sizes, int n_in,
                              void* d_out, int out_size)
{
    const float* raw_scale = (const float*)d_in[0];
    const float* raw_exp   = (const float*)d_in[1];
    const float* raw_rot   = (const float*)d_in[2];
    const float* trans     = (const float*)d_in[3];
    const float* points    = (const float*)d_in[4];
    float* out = (float*)d_out;

    const int P = in_sizes[4] / 3;
    const int threads = 256;
    const int blocks  = (P + threads - 1) / threads;
    superq_kernel<<<blocks, threads>>>(raw_scale, raw_exp, raw_rot, trans,
                                       points, out, P);
}